// round 3
// baseline (speedup 1.0000x reference)
#include <cuda_runtime.h>
#include <math.h>

// Problem dims
#define FDIM 2048
#define BDIM 2
#define HDIM 1024
#define NHEAD 16
#define EDIM 64
#define MROWS (FDIM * BDIM)      // 4096
#define N3 (3 * HDIM)            // 3072
#define MASK_ELEMS (BDIM * FDIM * FDIM)   // 8388608

// Scratch: per-head layouts [b*16+n][F][E] for q/k/v; ctx as [F*B, 1024]
__device__ float g_q[(size_t)BDIM * NHEAD * FDIM * EDIM];
__device__ float g_k[(size_t)BDIM * NHEAD * FDIM * EDIM];
__device__ float g_v[(size_t)BDIM * NHEAD * FDIM * EDIM];
__device__ float g_ctx[(size_t)MROWS * HDIM];
__device__ unsigned char g_mask[(size_t)MASK_ELEMS];
__device__ int g_mask_is_u8;

// ---------------------------------------------------------------------------
// Mask dtype sniffer: if the raw buffer holds uint8 bools, u32 words of
// random 0/1 BYTES are >1 almost surely; int32 bools give words in {0,1}.
// ---------------------------------------------------------------------------
__global__ void detect_mask_kernel(const unsigned int* __restrict__ raw)
{
    __shared__ int found;
    if (threadIdx.x == 0) found = 0;
    __syncthreads();
    int local = 0;
    for (int i = threadIdx.x; i < 4096; i += blockDim.x)
        if (raw[i] > 1u) local = 1;
    if (local) atomicOr(&found, 1);
    __syncthreads();
    if (threadIdx.x == 0) g_mask_is_u8 = found;
}

// Canonicalize mask to uint8 in g_mask (4 elems per thread).
__global__ void convert_mask_kernel(const void* __restrict__ raw)
{
    int i4 = blockIdx.x * blockDim.x + threadIdx.x;   // group of 4 elements
    if (i4 >= MASK_ELEMS / 4) return;
    uchar4 o;
    if (g_mask_is_u8) {
        o = ((const uchar4*)raw)[i4];
        o.x = o.x ? 1 : 0; o.y = o.y ? 1 : 0; o.z = o.z ? 1 : 0; o.w = o.w ? 1 : 0;
    } else {
        int4 v = ((const int4*)raw)[i4];
        o.x = v.x ? 1 : 0; o.y = v.y ? 1 : 0; o.z = v.z ? 1 : 0; o.w = v.w ? 1 : 0;
    }
    ((uchar4*)g_mask)[i4] = o;
}

// ---------------------------------------------------------------------------
// 128x128x16 register-blocked SGEMM, 256 threads, 8x8 micro-tile.
// EPI==0: C = A*B + bias, scattered into g_q/g_k/g_v per-head layout.
// EPI==1: C = A*B written dense to C (no bias).
// ---------------------------------------------------------------------------
template <int EPI>
__global__ __launch_bounds__(256) void gemm128(
    const float* __restrict__ A, const float* __restrict__ Bm,
    const float* __restrict__ bias, float* __restrict__ C,
    int Nn, int K)
{
    __shared__ float As[16][132];  // transposed A tile, padded
    __shared__ float Bs[16][128];

    const int tid = threadIdx.x;
    const int tx = tid & 15, ty = tid >> 4;
    const int m0 = blockIdx.y * 128, n0 = blockIdx.x * 128;

    float acc[8][8];
#pragma unroll
    for (int i = 0; i < 8; i++)
#pragma unroll
        for (int j = 0; j < 8; j++) acc[i][j] = 0.0f;

    for (int k0 = 0; k0 < K; k0 += 16) {
        // A tile 128x16 -> transposed into As[k][m]
#pragma unroll
        for (int p = 0; p < 2; p++) {
            int L = p * 256 + tid;
            int row = L >> 2, k4 = (L & 3) << 2;
            float4 v = *(const float4*)(A + (m0 + row) * K + k0 + k4);
            As[k4 + 0][row] = v.x;
            As[k4 + 1][row] = v.y;
            As[k4 + 2][row] = v.z;
            As[k4 + 3][row] = v.w;
        }
        // B tile 16x128
#pragma unroll
        for (int p = 0; p < 2; p++) {
            int L = p * 256 + tid;
            int row = L >> 5, n4 = (L & 31) << 2;
            *(float4*)&Bs[row][n4] = *(const float4*)(Bm + (k0 + row) * Nn + n0 + n4);
        }
        __syncthreads();

#pragma unroll
        for (int k = 0; k < 16; k++) {
            float a[8], b[8];
            *(float4*)&a[0] = *(float4*)&As[k][ty * 8];
            *(float4*)&a[4] = *(float4*)&As[k][ty * 8 + 4];
            *(float4*)&b[0] = *(float4*)&Bs[k][tx * 8];
            *(float4*)&b[4] = *(float4*)&Bs[k][tx * 8 + 4];
#pragma unroll
            for (int i = 0; i < 8; i++)
#pragma unroll
                for (int j = 0; j < 8; j++) acc[i][j] += a[i] * b[j];
        }
        __syncthreads();
    }

    if (EPI == 0) {
        // qkv scatter: col d -> head n=d/192, r=d%192, kind=r/64, e=r%64
#pragma unroll
        for (int i = 0; i < 8; i++) {
            int m = m0 + ty * 8 + i;
            int f = m >> 1, bb = m & 1;  // m = f*B + b
#pragma unroll
            for (int j = 0; j < 8; j++) {
                int d = n0 + tx * 8 + j;
                int nh = d / 192;
                int r = d - nh * 192;
                int kind = r >> 6, e = r & 63;
                float val = acc[i][j] + bias[d];
                float* dst = (kind == 0) ? g_q : (kind == 1) ? g_k : g_v;
                dst[(((bb << 4) + nh) * FDIM + f) * EDIM + e] = val;
            }
        }
    } else {
#pragma unroll
        for (int i = 0; i < 8; i++) {
            int m = m0 + ty * 8 + i;
            float* cp = C + m * Nn + n0 + tx * 8;
            *(float4*)cp = make_float4(acc[i][0], acc[i][1], acc[i][2], acc[i][3]);
            *((float4*)cp + 1) = make_float4(acc[i][4], acc[i][5], acc[i][6], acc[i][7]);
        }
    }
}

// ---------------------------------------------------------------------------
// Flash attention: one block = one (head, 128-query-row tile).
// 256 threads (tx 0..15 over 4-col groups, ty 0..15 over 8-row groups).
// Online softmax; scale (1/8) folded into Q load; mask -> -10000.
// ---------------------------------------------------------------------------
#define QS_STR 65
#define KS_STR 65
#define VS_STR 68
#define PS_STR 68
#define ATTN_SMEM_FLOATS (128 * QS_STR + 64 * KS_STR + 64 * VS_STR + 128 * PS_STR)
#define ATTN_SMEM_BYTES (ATTN_SMEM_FLOATS * 4)

__global__ __launch_bounds__(256) void attn_kernel(float* __restrict__ ctxout)
{
    extern __shared__ float sm[];
    float* Qs = sm;                      // [128][65]
    float* Ks = Qs + 128 * QS_STR;       // [64][65]
    float* Vs = Ks + 64 * KS_STR;        // [64][68]
    float* Ps = Vs + 64 * VS_STR;        // [128][68]

    const int tid = threadIdx.x;
    const int tx = tid & 15, ty = tid >> 4;
    const int head = blockIdx.y;
    const int b = head >> 4, n = head & 15;
    const int f0 = blockIdx.x * 128;

    const float* qh = g_q + (size_t)head * FDIM * EDIM;
    const float* kh = g_k + (size_t)head * FDIM * EDIM;
    const float* vh = g_v + (size_t)head * FDIM * EDIM;
    const unsigned char* mbase = g_mask + (size_t)b * FDIM * FDIM;

    // Load Q tile (scaled by 1/sqrt(E) = 0.125)
#pragma unroll
    for (int p = 0; p < 8; p++) {
        int L = p * 256 + tid;
        int r = L >> 4, c4 = (L & 15) << 2;
        float4 v = *(const float4*)(qh + (f0 + r) * EDIM + c4);
        Qs[r * QS_STR + c4 + 0] = v.x * 0.125f;
        Qs[r * QS_STR + c4 + 1] = v.y * 0.125f;
        Qs[r * QS_STR + c4 + 2] = v.z * 0.125f;
        Qs[r * QS_STR + c4 + 3] = v.w * 0.125f;
    }

    float mrow[8], lrow[8], cacc[8][4];
#pragma unroll
    for (int i = 0; i < 8; i++) {
        mrow[i] = -1e30f;
        lrow[i] = 0.0f;
#pragma unroll
        for (int j = 0; j < 4; j++) cacc[i][j] = 0.0f;
    }

    for (int t0 = 0; t0 < FDIM; t0 += 64) {
        // Load K, V tiles (64x64 each)
#pragma unroll
        for (int p = 0; p < 4; p++) {
            int L = p * 256 + tid;
            int r = L >> 4, c4 = (L & 15) << 2;
            float4 kv = *(const float4*)(kh + (t0 + r) * EDIM + c4);
            Ks[r * KS_STR + c4 + 0] = kv.x;
            Ks[r * KS_STR + c4 + 1] = kv.y;
            Ks[r * KS_STR + c4 + 2] = kv.z;
            Ks[r * KS_STR + c4 + 3] = kv.w;
            float4 vv = *(const float4*)(vh + (t0 + r) * EDIM + c4);
            *(float4*)&Vs[r * VS_STR + c4] = vv;
        }
        __syncthreads();

        // S = Q * K^T  (8 rows x 4 cols per thread)
        float s[8][4];
#pragma unroll
        for (int i = 0; i < 8; i++)
#pragma unroll
            for (int j = 0; j < 4; j++) s[i][j] = 0.0f;

#pragma unroll 8
        for (int e = 0; e < 64; e++) {
            float kr0 = Ks[(tx * 4 + 0) * KS_STR + e];
            float kr1 = Ks[(tx * 4 + 1) * KS_STR + e];
            float kr2 = Ks[(tx * 4 + 2) * KS_STR + e];
            float kr3 = Ks[(tx * 4 + 3) * KS_STR + e];
#pragma unroll
            for (int i = 0; i < 8; i++) {
                float qv = Qs[(ty * 8 + i) * QS_STR + e];
                s[i][0] += qv * kr0;
                s[i][1] += qv * kr1;
                s[i][2] += qv * kr2;
                s[i][3] += qv * kr3;
            }
        }

        // mask + online softmax update
#pragma unroll
        for (int i = 0; i < 8; i++) {
            int f = f0 + ty * 8 + i;
            uchar4 mv = *(const uchar4*)(mbase + (size_t)f * FDIM + t0 + tx * 4);
            if (!mv.x) s[i][0] = -10000.0f;
            if (!mv.y) s[i][1] = -10000.0f;
            if (!mv.z) s[i][2] = -10000.0f;
            if (!mv.w) s[i][3] = -10000.0f;

            float mt = fmaxf(fmaxf(s[i][0], s[i][1]), fmaxf(s[i][2], s[i][3]));
#pragma unroll
            for (int o = 1; o < 16; o <<= 1)
                mt = fmaxf(mt, __shfl_xor_sync(0xffffffffu, mt, o));

            float mnew = fmaxf(mrow[i], mt);
            float corr = __expf(mrow[i] - mnew);
            mrow[i] = mnew;

            float ps = 0.0f;
#pragma unroll
            for (int j = 0; j < 4; j++) {
                s[i][j] = __expf(s[i][j] - mnew);
                ps += s[i][j];
            }
#pragma unroll
            for (int o = 1; o < 16; o <<= 1)
                ps += __shfl_xor_sync(0xffffffffu, ps, o);

            lrow[i] = lrow[i] * corr + ps;
#pragma unroll
            for (int j = 0; j < 4; j++) cacc[i][j] *= corr;

#pragma unroll
            for (int j = 0; j < 4; j++)
                Ps[(ty * 8 + i) * PS_STR + tx * 4 + j] = s[i][j];
        }
        __syncthreads();

        // ctx += P * V
#pragma unroll 8
        for (int t = 0; t < 64; t++) {
            float4 vv = *(const float4*)&Vs[t * VS_STR + tx * 4];
#pragma unroll
            for (int i = 0; i < 8; i++) {
                float pv = Ps[(ty * 8 + i) * PS_STR + t];
                cacc[i][0] += pv * vv.x;
                cacc[i][1] += pv * vv.y;
                cacc[i][2] += pv * vv.z;
                cacc[i][3] += pv * vv.w;
            }
        }
        __syncthreads();
    }

    // Normalize and write ctx: [f][b][n*64 + c]
#pragma unroll
    for (int i = 0; i < 8; i++) {
        float inv = 1.0f / lrow[i];
        int f = f0 + ty * 8 + i;
        float4 o = make_float4(cacc[i][0] * inv, cacc[i][1] * inv,
                               cacc[i][2] * inv, cacc[i][3] * inv);
        *(float4*)(ctxout + ((size_t)f * BDIM + b) * HDIM + n * EDIM + tx * 4) = o;
    }
}

__global__ void tail_kernel(const float* __restrict__ b_out,
                            float* __restrict__ dst, int nvals)
{
    int i = blockIdx.x * blockDim.x + threadIdx.x;
    if (i < nvals) dst[i] = b_out[i];
}

extern "C" void kernel_launch(void* const* d_in, const int* in_sizes, int n_in,
                              void* d_out, int out_size)
{
    // Identify inputs by unique element counts (robust to metadata ordering).
    const float* q_input = nullptr;
    const void* mask_raw = nullptr;
    const float* w_qkv = nullptr;
    const float* b_qkv = nullptr;
    const float* w_out = nullptr;
    const float* b_out = nullptr;
    for (int i = 0; i < n_in; i++) {
        switch (in_sizes[i]) {
            case 4194304: q_input = (const float*)d_in[i]; break;   // F*B*H
            case 8388608: mask_raw = d_in[i]; break;                // B*F*F
            case 3145728: w_qkv = (const float*)d_in[i]; break;     // H*3H
            case 3072:    b_qkv = (const float*)d_in[i]; break;     // 3H
            case 1048576: w_out = (const float*)d_in[i]; break;     // N*E*H
            case 1024:    b_out = (const float*)d_in[i]; break;     // H
            default: break;
        }
    }
    float* out = (float*)d_out;

    cudaFuncSetAttribute(attn_kernel,
                         cudaFuncAttributeMaxDynamicSharedMemorySize,
                         ATTN_SMEM_BYTES);

    // 0) Canonicalize mask (handles uint8-bool OR int32-bool storage)
    detect_mask_kernel<<<1, 256>>>((const unsigned int*)mask_raw);
    convert_mask_kernel<<<(MASK_ELEMS / 4 + 255) / 256, 256>>>(mask_raw);

    // 1) QKV projection + scatter to per-head layout
    gemm128<0><<<dim3(N3 / 128, MROWS / 128), 256>>>(
        q_input, w_qkv, b_qkv, (float*)nullptr, N3, HDIM);

    // 2) Flash attention per (head, 128-row q tile)
    attn_kernel<<<dim3(FDIM / 128, BDIM * NHEAD), 256, ATTN_SMEM_BYTES>>>(g_ctx);

    // 3) Output projection (no bias, per reference)
    gemm128<1><<<dim3(HDIM / 128, MROWS / 128), 256>>>(
        g_ctx, w_out, (const float*)nullptr, out, HDIM, HDIM);

    // 4) b_out tail, if the harness packs the tuple (out, b_out)
    int tail = out_size - MROWS * HDIM;
    if (tail > 0) {
        int nvals = tail < HDIM ? tail : HDIM;
        tail_kernel<<<(nvals + 255) / 256, 256>>>(b_out, out + MROWS * HDIM, nvals);
    }
}